// round 2
// baseline (speedup 1.0000x reference)
#include <cuda_runtime.h>
#include <cuda_bf16.h>
#include <cstdint>

// ---------------- problem constants ----------------
#define T_SEQ 512
#define BB    16
#define HH    1024
#define EE    512
#define VV    32000
#define G4H   4096
#define M_ROWS (BB * T_SEQ)                     // 8192
#define LOGN  ((size_t)M_ROWS * (size_t)VV)     // 262,144,000

// ---------------- device scratch (static globals: allowed) ----------------
__device__ float g_xg[(size_t)T_SEQ * BB * G4H];   // 134 MB, reused per layer
__device__ float g_out0[(size_t)M_ROWS * HH];      // layer-0 h sequence [b][t][H]
__device__ float g_out1[(size_t)M_ROWS * HH];      // layer-1 h sequence [b][t][H]
__device__ float g_hbuf[2 * HH * BB];              // double buffer, [j][b] layout
__device__ unsigned g_bar;                         // zero-init
__device__ volatile unsigned g_epoch;              // zero-init

// ---------------- f32x2 packed-FMA helpers ----------------
typedef unsigned long long u64;
__device__ __forceinline__ u64 pack2(float v) {
    u64 r; asm("mov.b64 %0, {%1, %1};" : "=l"(r) : "f"(v)); return r;
}
__device__ __forceinline__ void ffma2(u64& c, u64 a, u64 b) {
    asm("fma.rn.f32x2 %0, %1, %2, %0;" : "+l"(c) : "l"(a), "l"(b));
}
__device__ __forceinline__ float2 unpack2(u64 v) {
    float lo, hi; asm("mov.b64 {%0, %1}, %2;" : "=f"(lo), "=f"(hi) : "l"(v));
    float2 f; f.x = lo; f.y = hi; return f;
}

// ---------------- GEMM: C[M,N] = A[M,K] @ W[N,K]^T + bias1 (+ bias2) ----------
// GATHER: A row m is emb[gidx[m]].  REMAP: output row (b*T+t) -> (t*B+b).
// 128x128 tile, 256 threads, 8x8 per-thread microtile via f32x2 FFMA2.
// N-fragment = two 4-wide strips (tx*4 and 64+tx*4) => 2-way LDS conflicts max.
template<bool GATHER, bool REMAP>
__global__ __launch_bounds__(256)
void sgemm_tn(const float* __restrict__ A, const float* __restrict__ W,
              const float* __restrict__ bias1, const float* __restrict__ bias2,
              float* __restrict__ C, int M, int N, int K,
              const int* __restrict__ gidx)
{
    __shared__ float As[16][132];
    __shared__ float Bs[16][132];
    const int tid = threadIdx.x;
    const int tx = tid & 15, ty = tid >> 4;   // tx -> N strips, ty -> M strip
    const int m0 = blockIdx.y * 128, n0 = blockIdx.x * 128;
    const int lrow = tid >> 2;                // 0..63
    const int lc4  = (tid & 3) * 4;           // 0,4,8,12

    u64 acc[8][4];
#pragma unroll
    for (int i = 0; i < 8; i++)
#pragma unroll
        for (int j = 0; j < 4; j++) acc[i][j] = 0ULL;

    for (int kt = 0; kt < K; kt += 16) {
#pragma unroll
        for (int rr = 0; rr < 128; rr += 64) {
            int m = m0 + lrow + rr;
            const float* ap = GATHER ? (A + (size_t)gidx[m] * K) : (A + (size_t)m * K);
            float4 v = *(const float4*)(ap + kt + lc4);
            As[lc4 + 0][lrow + rr] = v.x; As[lc4 + 1][lrow + rr] = v.y;
            As[lc4 + 2][lrow + rr] = v.z; As[lc4 + 3][lrow + rr] = v.w;
            const float* wp = W + (size_t)(n0 + lrow + rr) * K;
            float4 u = *(const float4*)(wp + kt + lc4);
            Bs[lc4 + 0][lrow + rr] = u.x; Bs[lc4 + 1][lrow + rr] = u.y;
            Bs[lc4 + 2][lrow + rr] = u.z; Bs[lc4 + 3][lrow + rr] = u.w;
        }
        __syncthreads();
#pragma unroll
        for (int k = 0; k < 16; k++) {
            float4 a0 = *(const float4*)&As[k][ty * 8];
            float4 a1 = *(const float4*)&As[k][ty * 8 + 4];
            ulonglong2 bA = *(const ulonglong2*)&Bs[k][tx * 4];
            ulonglong2 bB = *(const ulonglong2*)&Bs[k][64 + tx * 4];
            float av[8] = {a0.x, a0.y, a0.z, a0.w, a1.x, a1.y, a1.z, a1.w};
#pragma unroll
            for (int i = 0; i < 8; i++) {
                u64 ap2 = pack2(av[i]);
                ffma2(acc[i][0], ap2, bA.x); ffma2(acc[i][1], ap2, bA.y);
                ffma2(acc[i][2], ap2, bB.x); ffma2(acc[i][3], ap2, bB.y);
            }
        }
        __syncthreads();
    }

    int ncol[4] = {tx * 4, tx * 4 + 2, 64 + tx * 4, 64 + tx * 4 + 2};
    float bv[4][2];
#pragma unroll
    for (int j4 = 0; j4 < 4; j4++) {
#pragma unroll
        for (int e = 0; e < 2; e++) {
            int gn = n0 + ncol[j4] + e;
            float b = bias1[gn];
            if (bias2) b += bias2[gn];
            bv[j4][e] = b;
        }
    }
#pragma unroll
    for (int i = 0; i < 8; i++) {
        int gm = m0 + ty * 8 + i;
        size_t orow = REMAP ? (size_t)((gm & (T_SEQ - 1)) * BB + (gm >> 9)) : (size_t)gm;
        float* crow = C + orow * (size_t)N + n0;
#pragma unroll
        for (int j4 = 0; j4 < 4; j4++) {
            float2 c2 = unpack2(acc[i][j4]);
            float2 o; o.x = c2.x + bv[j4][0]; o.y = c2.y + bv[j4][1];
            *(float2*)(crow + ncol[j4]) = o;
        }
    }
}

// ---------------- h0 transpose fill: g_hbuf[0][j*16+b] = h0[b][j] --------------
__global__ void fill_h0_kernel(const float* __restrict__ h0)
{
    int i = blockIdx.x * 256 + threadIdx.x;
    if (i < BB * HH) {
        int b = i >> 10, j = i & (HH - 1);
        g_hbuf[j * BB + b] = h0[i];
    }
}

// ---------------- persistent LSTM scan -----------------------------------------
// 128 CTAs x 256 threads; 208KB smem => 1 CTA/SM, all co-resident (safe grid bar).
// CTA owns 8 output channels j => 32 gate rows. Whh slice cached transposed in
// smem (loaded once, reused 512 steps). h staged to smem per step via __ldcg.
__device__ __forceinline__ float sigm(float x) { return 1.f / (1.f + expf(-x)); }

__global__ __launch_bounds__(256)
void lstm_scan(const float* __restrict__ xg, const float* __restrict__ Whh,
               const float* __restrict__ c0, float* __restrict__ outSeq,
               float* __restrict__ state_out, int layer)
{
    extern __shared__ float sm[];
    float* ws  = sm;                          // [1024][32]  128 KB (ws[k*32+r])
    float* hs  = sm + HH * 32;                // [1024][16]   64 KB (hs[k*16+b])
    float* red = sm + HH * 32 + HH * 16;      // [32][16][8]  16 KB
    const int tid = threadIdx.x, cta = blockIdx.x;
    const int warp = tid >> 5, lane = tid & 31;
    const int rg = lane & 7, bg = lane >> 3;  // 8 row-groups x 4 batch-groups

    // load Whh slice transposed (once; reused for all 512 steps)
    for (int idx = tid; idx < 32 * 256; idx += 256) {
        int r  = idx >> 8;                    // local row 0..31 (r = g*8 + jl)
        int k4 = (idx & 255) * 4;
        int grow = (r >> 3) * HH + cta * 8 + (r & 7);
        float4 w = *(const float4*)(Whh + (size_t)grow * HH + k4);
        ws[(k4 + 0) * 32 + r] = w.x; ws[(k4 + 1) * 32 + r] = w.y;
        ws[(k4 + 2) * 32 + r] = w.z; ws[(k4 + 3) * 32 + r] = w.w;
    }

    const int fb = tid >> 3, fj = tid & 7;    // finalize mapping (tid < 128)
    float c_reg = 0.f;
    if (tid < 128) c_reg = c0[fb * HH + cta * 8 + fj];

    int cur = 0;
    const int k0 = warp * 128;
    for (int t = 0; t < T_SEQ; ++t) {
        // stage h_prev into smem (L2 loads: L1 may be stale within this launch)
        const float4* hb = (const float4*)(g_hbuf + cur * (HH * BB));
        float4* hs4 = (float4*)hs;
#pragma unroll
        for (int i = 0; i < 16; ++i) hs4[tid + i * 256] = __ldcg(hb + tid + i * 256);
        __syncthreads();

        float acc[4][4];
#pragma unroll
        for (int i = 0; i < 4; i++)
#pragma unroll
            for (int j = 0; j < 4; j++) acc[i][j] = 0.f;

#pragma unroll 4
        for (int k = k0; k < k0 + 128; ++k) {
            float4 hv = *(const float4*)&hs[k * 16 + bg * 4];
            float4 wv = *(const float4*)&ws[k * 32 + rg * 4];
            acc[0][0] += wv.x * hv.x; acc[0][1] += wv.x * hv.y; acc[0][2] += wv.x * hv.z; acc[0][3] += wv.x * hv.w;
            acc[1][0] += wv.y * hv.x; acc[1][1] += wv.y * hv.y; acc[1][2] += wv.y * hv.z; acc[1][3] += wv.y * hv.w;
            acc[2][0] += wv.z * hv.x; acc[2][1] += wv.z * hv.y; acc[2][2] += wv.z * hv.z; acc[2][3] += wv.z * hv.w;
            acc[3][0] += wv.w * hv.x; acc[3][1] += wv.w * hv.y; acc[3][2] += wv.w * hv.z; acc[3][3] += wv.w * hv.w;
        }
#pragma unroll
        for (int i = 0; i < 4; i++)
#pragma unroll
            for (int j = 0; j < 4; j++)
                red[(((rg * 4 + i) << 4) + bg * 4 + j) * 8 + warp] = acc[i][j];
        __syncthreads();

        if (tid < 128) {
            int jg = cta * 8 + fj;
            float s[4];
#pragma unroll
            for (int g = 0; g < 4; ++g) {
                const float* rp = &red[(((g * 8 + fj) << 4) + fb) * 8];
                float sum = rp[0] + rp[1] + rp[2] + rp[3] + rp[4] + rp[5] + rp[6] + rp[7];
                s[g] = sum + xg[((size_t)(t * BB + fb)) * G4H + g * HH + jg];
            }
            float ci = sigm(s[0]), cf = sigm(s[1]);
            float cg = tanhf(s[2]), co = sigm(s[3]);
            c_reg = cf * c_reg + ci * cg;
            float hnew = co * tanhf(c_reg);
            outSeq[((size_t)fb * T_SEQ + t) * HH + jg] = hnew;
            g_hbuf[(cur ^ 1) * (HH * BB) + jg * BB + fb] = hnew;
            if (t == T_SEQ - 1 && state_out) {
                state_out[(size_t)layer * BB * HH + fb * HH + jg] = hnew;
                state_out[2 * (size_t)BB * HH + (size_t)layer * BB * HH + fb * HH + jg] = c_reg;
            }
        }

        // ---- grid barrier (sense-reversal; 128 co-resident CTAs) ----
        __syncthreads();
        if (tid == 0) {
            unsigned e = g_epoch;
            __threadfence();
            if (atomicAdd(&g_bar, 1u) == (unsigned)gridDim.x - 1u) {
                g_bar = 0;
                __threadfence();
                g_epoch = e + 1;
            } else {
                while (g_epoch == e) { }
            }
        }
        __syncthreads();
        cur ^= 1;
    }
}

// ---------------- launch -------------------------------------------------------
extern "C" void kernel_launch(void* const* d_in, const int* in_sizes, int n_in,
                              void* d_out, int out_size)
{
    const int*   x    = (const int*)  d_in[0];
    const float* h0   = (const float*)d_in[1];
    const float* c0   = (const float*)d_in[2];
    const float* emb  = (const float*)d_in[3];
    const float* Wih0 = (const float*)d_in[4];
    const float* Whh0 = (const float*)d_in[5];
    const float* bih0 = (const float*)d_in[6];
    const float* bhh0 = (const float*)d_in[7];
    const float* Wih1 = (const float*)d_in[8];
    const float* Whh1 = (const float*)d_in[9];
    const float* bih1 = (const float*)d_in[10];
    const float* bhh1 = (const float*)d_in[11];
    const float* Wfc  = (const float*)d_in[12];
    const float* bfc  = (const float*)d_in[13];
    float* out = (float*)d_out;

    float *xg, *o0, *o1;
    cudaGetSymbolAddress((void**)&xg, g_xg);
    cudaGetSymbolAddress((void**)&o0, g_out0);
    cudaGetSymbolAddress((void**)&o1, g_out1);

    float* state_out = ((size_t)out_size >= LOGN + 4 * BB * HH) ? (out + LOGN) : nullptr;

    const int SMEM_SCAN = (HH * 32 + HH * 16 + 32 * 16 * 8) * 4;   // 212,992 B
    cudaFuncSetAttribute(lstm_scan, cudaFuncAttributeMaxDynamicSharedMemorySize, SMEM_SCAN);

    // layer 0: xg0 = gather(emb,x) @ Wih0^T + bih0 + bhh0   -> [t*B+b, 4H]
    sgemm_tn<true, true><<<dim3(G4H / 128, M_ROWS / 128), 256>>>(
        emb, Wih0, bih0, bhh0, xg, M_ROWS, G4H, EE, x);
    fill_h0_kernel<<<(BB * HH + 255) / 256, 256>>>(h0);
    lstm_scan<<<128, 256, SMEM_SCAN>>>(xg, Whh0, c0, o0, state_out, 0);

    // layer 1: xg1 = out0 @ Wih1^T + bih1 + bhh1
    sgemm_tn<false, true><<<dim3(G4H / 128, M_ROWS / 128), 256>>>(
        o0, Wih1, bih1, bhh1, xg, M_ROWS, G4H, HH, nullptr);
    fill_h0_kernel<<<(BB * HH + 255) / 256, 256>>>(h0 + BB * HH);
    lstm_scan<<<128, 256, SMEM_SCAN>>>(xg, Whh1, c0 + BB * HH, o1, state_out, 1);

    // logits = out1 @ Wfc^T + bfc   -> [B*T, V]
    sgemm_tn<false, false><<<dim3(VV / 128, M_ROWS / 128), 256>>>(
        o1, Wfc, bfc, nullptr, out, M_ROWS, VV, HH, nullptr);
}

// round 4
// speedup vs baseline: 1.3403x; 1.3403x over previous
#include <cuda_runtime.h>
#include <cuda_bf16.h>
#include <cstdint>

// ---------------- problem constants ----------------
#define T_SEQ 512
#define BB    16
#define HH    1024
#define EE    512
#define VV    32000
#define G4H   4096
#define M_ROWS (BB * T_SEQ)                     // 8192
#define LOGN  ((size_t)M_ROWS * (size_t)VV)     // 262,144,000
#define FCK   3072                              // K-expanded (hi|hi|lo)x(hi|lo|hi)

// ---------------- device scratch (static globals: allowed) ----------------
__device__ float g_xg[(size_t)T_SEQ * BB * G4H];   // 134 MB, reused per layer
__device__ float g_out0[(size_t)M_ROWS * HH];      // layer-0 h sequence
__device__ float g_out1[(size_t)M_ROWS * HH];      // layer-1 h sequence
__device__ float g_hbuf[2 * HH * BB];              // double buffer, [j][b] layout
__device__ unsigned g_bar;                         // zero-init
__device__ volatile unsigned g_epoch;              // zero-init
__device__ __nv_bfloat16 g_A2[(size_t)M_ROWS * FCK];  // 50 MB  [Ahi|Ahi|Alo]
__device__ __nv_bfloat16 g_B2[(size_t)VV * FCK];      // 197 MB [Bhi|Blo|Bhi]

// ---------------- f32x2 packed-FMA helpers ----------------
typedef unsigned long long u64;
__device__ __forceinline__ u64 pack2(float v) {
    u64 r; asm("mov.b64 %0, {%1, %1};" : "=l"(r) : "f"(v)); return r;
}
__device__ __forceinline__ void ffma2(u64& c, u64 a, u64 b) {
    asm("fma.rn.f32x2 %0, %1, %2, %0;" : "+l"(c) : "l"(a), "l"(b));
}
__device__ __forceinline__ float2 unpack2(u64 v) {
    float lo, hi; asm("mov.b64 {%0, %1}, %2;" : "=f"(lo), "=f"(hi) : "l"(v));
    float2 f; f.x = lo; f.y = hi; return f;
}

// ---------------- base-ISA async-copy / ldmatrix / mma helpers ----------------
__device__ __forceinline__ uint32_t smem_u32(const void* p) {
    uint32_t a;
    asm("{ .reg .u64 t; cvta.to.shared.u64 t, %1; cvt.u32.u64 %0, t; }" : "=r"(a) : "l"(p));
    return a;
}
__device__ __forceinline__ void cpa16(uint32_t dst, const void* src) {
    asm volatile("cp.async.cg.shared.global [%0], [%1], 16;" :: "r"(dst), "l"(src));
}
__device__ __forceinline__ void cpa_commit() { asm volatile("cp.async.commit_group;" ::: "memory"); }
template<int N> __device__ __forceinline__ void cpa_wait() {
    asm volatile("cp.async.wait_group %0;" :: "n"(N) : "memory");
}
__device__ __forceinline__ void ldsm4(uint32_t& r0, uint32_t& r1, uint32_t& r2, uint32_t& r3,
                                      uint32_t a) {
    asm volatile("ldmatrix.sync.aligned.m8n8.x4.shared.b16 {%0,%1,%2,%3}, [%4];"
                 : "=r"(r0), "=r"(r1), "=r"(r2), "=r"(r3) : "r"(a));
}
__device__ __forceinline__ void mma_bf16(float* c, const uint32_t* a, const uint32_t* b) {
    asm volatile(
        "mma.sync.aligned.m16n8k16.row.col.f32.bf16.bf16.f32 "
        "{%0,%1,%2,%3}, {%4,%5,%6,%7}, {%8,%9}, {%0,%1,%2,%3};"
        : "+f"(c[0]), "+f"(c[1]), "+f"(c[2]), "+f"(c[3])
        : "r"(a[0]), "r"(a[1]), "r"(a[2]), "r"(a[3]), "r"(b[0]), "r"(b[1]));
}

// ---------------- split-expand: fp32 [rows][1024] -> bf16 [rows][3072] ----------
// MODE 0 (activations): segs (hi, hi, lo).  MODE 1 (weights): segs (hi, lo, hi).
template<int MODE>
__global__ __launch_bounds__(256)
void split3(const float* __restrict__ src, __nv_bfloat16* __restrict__ dst, int n4)
{
    int i = blockIdx.x * 256 + threadIdx.x;
    if (i >= n4) return;
    float4 v = ((const float4*)src)[i];
    __nv_bfloat16 h0 = __float2bfloat16(v.x), h1 = __float2bfloat16(v.y);
    __nv_bfloat16 h2 = __float2bfloat16(v.z), h3 = __float2bfloat16(v.w);
    __nv_bfloat16 l0 = __float2bfloat16(v.x - __bfloat162float(h0));
    __nv_bfloat16 l1 = __float2bfloat16(v.y - __bfloat162float(h1));
    __nv_bfloat16 l2 = __float2bfloat16(v.z - __bfloat162float(h2));
    __nv_bfloat16 l3 = __float2bfloat16(v.w - __bfloat162float(h3));
    int row = i >> 8;                 // 256 float4 per 1024-wide row
    int col = (i & 255) * 4;
    __nv_bfloat162* d0 = (__nv_bfloat162*)(dst + (size_t)row * FCK + col);
    __nv_bfloat162* d1 = (__nv_bfloat162*)(dst + (size_t)row * FCK + 1024 + col);
    __nv_bfloat162* d2 = (__nv_bfloat162*)(dst + (size_t)row * FCK + 2048 + col);
    __nv_bfloat162 hA(h0, h1), hB(h2, h3), lA(l0, l1), lB(l2, l3);
    d0[0] = hA; d0[1] = hB;
    if (MODE == 0) { d1[0] = hA; d1[1] = hB; d2[0] = lA; d2[1] = lB; }
    else           { d1[0] = lA; d1[1] = lB; d2[0] = hA; d2[1] = hB; }
}

// ---------------- FC GEMM via HMMA (mma.sync bf16) ----------------------------
// C[8192, 32000] = A2[8192, 3072] @ B2[32000, 3072]^T + bias
// CTA tile 128x128, 8 warps of 64x32, BK=32, 3-stage cp.async pipeline.
// smem per stage: A 8KB + B 8KB, XOR-swizzled (chunk ^= (row>>1)&3) for
// conflict-free ldmatrix (rows alternate bank halves; xor spreads 16B cols).
#define FC_BK      32
#define FC_STAGE_B 16384
#define FC_NSTAGE  3
#define FC_SMEM    (FC_NSTAGE * FC_STAGE_B)     // 49152

__device__ __forceinline__ void fc_fill(uint32_t st, const __nv_bfloat16* a,
                                        const __nv_bfloat16* b, int tid)
{
#pragma unroll
    for (int i = tid; i < 512; i += 256) {
        int r = i >> 2, c = i & 3;
        uint32_t dst = st + r * 64 + ((c ^ ((r >> 1) & 3)) << 4);
        cpa16(dst, a + (size_t)r * FCK + c * 8);
    }
#pragma unroll
    for (int i = tid; i < 512; i += 256) {
        int r = i >> 2, c = i & 3;
        uint32_t dst = st + 8192 + r * 64 + ((c ^ ((r >> 1) & 3)) << 4);
        cpa16(dst, b + (size_t)r * FCK + c * 8);
    }
    cpa_commit();
}

__global__ __launch_bounds__(256, 2)
void fc_hmma(const __nv_bfloat16* __restrict__ A2, const __nv_bfloat16* __restrict__ B2,
             const float* __restrict__ bias, float* __restrict__ C)
{
    extern __shared__ char smem[];
    const uint32_t sbase = smem_u32(smem);
    const int tid = threadIdx.x, wid = tid >> 5, lane = tid & 31;
    const int warp_m = wid & 1, warp_n = wid >> 1;          // 2 x 4 warp grid
    const int m0 = blockIdx.x * 128;                         // M fast => B L2 reuse
    const int n0 = blockIdx.y * 128;

    const __nv_bfloat16* aG = A2 + (size_t)m0 * FCK;
    const __nv_bfloat16* bG = B2 + (size_t)n0 * FCK;

    // per-lane ldmatrix offsets within a stage
    uint32_t aoff[4][2], boff[2][2];
#pragma unroll
    for (int mi = 0; mi < 4; ++mi)
#pragma unroll
        for (int ks = 0; ks < 2; ++ks) {
            int row = warp_m * 64 + mi * 16 + (lane & 15);
            int ch  = ks * 2 + (lane >> 4);
            aoff[mi][ks] = row * 64 + ((ch ^ ((row >> 1) & 3)) << 4);
        }
#pragma unroll
    for (int bi = 0; bi < 2; ++bi)
#pragma unroll
        for (int ks = 0; ks < 2; ++ks) {
            int row = warp_n * 32 + bi * 16 + (lane & 7) + ((lane >> 4) << 3);
            int ch  = ks * 2 + ((lane >> 3) & 1);
            boff[bi][ks] = 8192 + row * 64 + ((ch ^ ((row >> 1) & 3)) << 4);
        }

    float acc[4][4][4];
#pragma unroll
    for (int i = 0; i < 4; i++)
#pragma unroll
        for (int j = 0; j < 4; j++)
#pragma unroll
            for (int e = 0; e < 4; e++) acc[i][j][e] = 0.f;

    const int NKB = FCK / FC_BK;                             // 96
    fc_fill(sbase,              aG,          bG,          tid);
    fc_fill(sbase + FC_STAGE_B, aG + FC_BK,  bG + FC_BK,  tid);

    for (int kb = 0; kb < NKB; ++kb) {
        const int s = kb % 3;
        cpa_wait<1>();
        __syncthreads();
        if (kb + 2 < NKB)
            fc_fill(sbase + ((kb + 2) % 3) * FC_STAGE_B,
                    aG + (size_t)(kb + 2) * FC_BK, bG + (size_t)(kb + 2) * FC_BK, tid);

        const uint32_t sb = sbase + s * FC_STAGE_B;
#pragma unroll
        for (int ks = 0; ks < 2; ++ks) {
            uint32_t a[4][4], b[2][4];
#pragma unroll
            for (int mi = 0; mi < 4; ++mi)
                ldsm4(a[mi][0], a[mi][1], a[mi][2], a[mi][3], sb + aoff[mi][ks]);
#pragma unroll
            for (int bi = 0; bi < 2; ++bi)
                ldsm4(b[bi][0], b[bi][1], b[bi][2], b[bi][3], sb + boff[bi][ks]);
#pragma unroll
            for (int mi = 0; mi < 4; ++mi)
#pragma unroll
                for (int ni = 0; ni < 4; ++ni)
                    mma_bf16(acc[mi][ni], a[mi], &b[ni >> 1][(ni & 1) * 2]);
        }
        __syncthreads();
    }

    // epilogue: direct f32 stores with bias
#pragma unroll
    for (int mi = 0; mi < 4; ++mi) {
        int r0 = m0 + warp_m * 64 + mi * 16 + (lane >> 2);
#pragma unroll
        for (int ni = 0; ni < 4; ++ni) {
            int col = n0 + warp_n * 32 + ni * 8 + (lane & 3) * 2;
            float2 bv = *(const float2*)(bias + col);
            float2 v0; v0.x = acc[mi][ni][0] + bv.x; v0.y = acc[mi][ni][1] + bv.y;
            float2 v1; v1.x = acc[mi][ni][2] + bv.x; v1.y = acc[mi][ni][3] + bv.y;
            *(float2*)(C + (size_t)r0 * VV + col) = v0;
            *(float2*)(C + (size_t)(r0 + 8) * VV + col) = v1;
        }
    }
}

// ---------------- GEMM: C[M,N] = A[M,K] @ W[N,K]^T + bias1 (+ bias2) ----------
// (FFMA2 path; used for the xg precomputes which feed the scans)
template<bool GATHER, bool REMAP>
__global__ __launch_bounds__(256)
void sgemm_tn(const float* __restrict__ A, const float* __restrict__ W,
              const float* __restrict__ bias1, const float* __restrict__ bias2,
              float* __restrict__ C, int M, int N, int K,
              const int* __restrict__ gidx)
{
    __shared__ float As[16][132];
    __shared__ float Bs[16][132];
    const int tid = threadIdx.x;
    const int tx = tid & 15, ty = tid >> 4;
    const int m0 = blockIdx.y * 128, n0 = blockIdx.x * 128;
    const int lrow = tid >> 2;
    const int lc4  = (tid & 3) * 4;

    u64 acc[8][4];
#pragma unroll
    for (int i = 0; i < 8; i++)
#pragma unroll
        for (int j = 0; j < 4; j++) acc[i][j] = 0ULL;

    for (int kt = 0; kt < K; kt += 16) {
#pragma unroll
        for (int rr = 0; rr < 128; rr += 64) {
            int m = m0 + lrow + rr;
            const float* ap = GATHER ? (A + (size_t)gidx[m] * K) : (A + (size_t)m * K);
            float4 v = *(const float4*)(ap + kt + lc4);
            As[lc4 + 0][lrow + rr] = v.x; As[lc4 + 1][lrow + rr] = v.y;
            As[lc4 + 2][lrow + rr] = v.z; As[lc4 + 3][lrow + rr] = v.w;
            const float* wp = W + (size_t)(n0 + lrow + rr) * K;
            float4 u = *(const float4*)(wp + kt + lc4);
            Bs[lc4 + 0][lrow + rr] = u.x; Bs[lc4 + 1][lrow + rr] = u.y;
            Bs[lc4 + 2][lrow + rr] = u.z; Bs[lc4 + 3][lrow + rr] = u.w;
        }
        __syncthreads();
#pragma unroll
        for (int k = 0; k < 16; k++) {
            float4 a0 = *(const float4*)&As[k][ty * 8];
            float4 a1 = *(const float4*)&As[k][ty * 8 + 4];
            ulonglong2 bA = *(const ulonglong2*)&Bs[k][tx * 4];
            ulonglong2 bB = *(const ulonglong2*)&Bs[k][64 + tx * 4];
            float av[8] = {a0.x, a0.y, a0.z, a0.w, a1.x, a1.y, a1.z, a1.w};
#pragma unroll
            for (int i = 0; i < 8; i++) {
                u64 ap2 = pack2(av[i]);
                ffma2(acc[i][0], ap2, bA.x); ffma2(acc[i][1], ap2, bA.y);
                ffma2(acc[i][2], ap2, bB.x); ffma2(acc[i][3], ap2, bB.y);
            }
        }
        __syncthreads();
    }

    int ncol[4] = {tx * 4, tx * 4 + 2, 64 + tx * 4, 64 + tx * 4 + 2};
    float bv[4][2];
#pragma unroll
    for (int j4 = 0; j4 < 4; j4++) {
#pragma unroll
        for (int e = 0; e < 2; e++) {
            int gn = n0 + ncol[j4] + e;
            float b = bias1[gn];
            if (bias2) b += bias2[gn];
            bv[j4][e] = b;
        }
    }
#pragma unroll
    for (int i = 0; i < 8; i++) {
        int gm = m0 + ty * 8 + i;
        size_t orow = REMAP ? (size_t)((gm & (T_SEQ - 1)) * BB + (gm >> 9)) : (size_t)gm;
        float* crow = C + orow * (size_t)N + n0;
#pragma unroll
        for (int j4 = 0; j4 < 4; j4++) {
            float2 c2 = unpack2(acc[i][j4]);
            float2 o; o.x = c2.x + bv[j4][0]; o.y = c2.y + bv[j4][1];
            *(float2*)(crow + ncol[j4]) = o;
        }
    }
}

// ---------------- h0 transpose fill: g_hbuf[0][j*16+b] = h0[b][j] --------------
__global__ void fill_h0_kernel(const float* __restrict__ h0)
{
    int i = blockIdx.x * 256 + threadIdx.x;
    if (i < BB * HH) {
        int b = i >> 10, j = i & (HH - 1);
        g_hbuf[j * BB + b] = h0[i];
    }
}

// ---------------- persistent LSTM scan -----------------------------------------
__device__ __forceinline__ float sigm(float x) { return 1.f / (1.f + expf(-x)); }

__global__ __launch_bounds__(256)
void lstm_scan(const float* __restrict__ xg, const float* __restrict__ Whh,
               const float* __restrict__ c0, float* __restrict__ outSeq,
               float* __restrict__ state_out, int layer)
{
    extern __shared__ float sm[];
    float* ws  = sm;                          // [1024][32]  128 KB
    float* hs  = sm + HH * 32;                // [1024][16]   64 KB
    float* red = sm + HH * 32 + HH * 16;      // [32][16][8]  16 KB
    const int tid = threadIdx.x, cta = blockIdx.x;
    const int warp = tid >> 5, lane = tid & 31;
    const int rg = lane & 7, bg = lane >> 3;

    for (int idx = tid; idx < 32 * 256; idx += 256) {
        int r  = idx >> 8;
        int k4 = (idx & 255) * 4;
        int grow = (r >> 3) * HH + cta * 8 + (r & 7);
        float4 w = *(const float4*)(Whh + (size_t)grow * HH + k4);
        ws[(k4 + 0) * 32 + r] = w.x; ws[(k4 + 1) * 32 + r] = w.y;
        ws[(k4 + 2) * 32 + r] = w.z; ws[(k4 + 3) * 32 + r] = w.w;
    }

    const int fb = tid >> 3, fj = tid & 7;
    float c_reg = 0.f;
    if (tid < 128) c_reg = c0[fb * HH + cta * 8 + fj];

    int cur = 0;
    const int k0 = warp * 128;
    for (int t = 0; t < T_SEQ; ++t) {
        const float4* hb = (const float4*)(g_hbuf + cur * (HH * BB));
        float4* hs4 = (float4*)hs;
#pragma unroll
        for (int i = 0; i < 16; ++i) hs4[tid + i * 256] = __ldcg(hb + tid + i * 256);
        __syncthreads();

        float acc[4][4];
#pragma unroll
        for (int i = 0; i < 4; i++)
#pragma unroll
            for (int j = 0; j < 4; j++) acc[i][j] = 0.f;

#pragma unroll 4
        for (int k = k0; k < k0 + 128; ++k) {
            float4 hv = *(const float4*)&hs[k * 16 + bg * 4];
            float4 wv = *(const float4*)&ws[k * 32 + rg * 4];
            acc[0][0] += wv.x * hv.x; acc[0][1] += wv.x * hv.y; acc[0][2] += wv.x * hv.z; acc[0][3] += wv.x * hv.w;
            acc[1][0] += wv.y * hv.x; acc[1][1] += wv.y * hv.y; acc[1][2] += wv.y * hv.z; acc[1][3] += wv.y * hv.w;
            acc[2][0] += wv.z * hv.x; acc[2][1] += wv.z * hv.y; acc[2][2] += wv.z * hv.z; acc[2][3] += wv.z * hv.w;
            acc[3][0] += wv.w * hv.x; acc[3][1] += wv.w * hv.y; acc[3][2] += wv.w * hv.z; acc[3][3] += wv.w * hv.w;
        }
#pragma unroll
        for (int i = 0; i < 4; i++)
#pragma unroll
            for (int j = 0; j < 4; j++)
                red[(((rg * 4 + i) << 4) + bg * 4 + j) * 8 + warp] = acc[i][j];
        __syncthreads();

        if (tid < 128) {
            int jg = cta * 8 + fj;
            float s[4];
#pragma unroll
            for (int g = 0; g < 4; ++g) {
                const float* rp = &red[(((g * 8 + fj) << 4) + fb) * 8];
                float sum = rp[0] + rp[1] + rp[2] + rp[3] + rp[4] + rp[5] + rp[6] + rp[7];
                s[g] = sum + xg[((size_t)(t * BB + fb)) * G4H + g * HH + jg];
            }
            float ci = sigm(s[0]), cf = sigm(s[1]);
            float cg = tanhf(s[2]), co = sigm(s[3]);
            c_reg = cf * c_reg + ci * cg;
            float hnew = co * tanhf(c_reg);
            outSeq[((size_t)fb * T_SEQ + t) * HH + jg] = hnew;
            g_hbuf[(cur ^ 1) * (HH * BB) + jg * BB + fb] = hnew;
            if (t == T_SEQ - 1 && state_out) {
                state_out[(size_t)layer * BB * HH + fb * HH + jg] = hnew;
                state_out[2 * (size_t)BB * HH + (size_t)layer * BB * HH + fb * HH + jg] = c_reg;
            }
        }

        __syncthreads();
        if (tid == 0) {
            unsigned e = g_epoch;
            __threadfence();
            if (atomicAdd(&g_bar, 1u) == (unsigned)gridDim.x - 1u) {
                g_bar = 0;
                __threadfence();
                g_epoch = e + 1;
            } else {
                while (g_epoch == e) { }
            }
        }
        __syncthreads();
        cur ^= 1;
    }
}

// ---------------- launch -------------------------------------------------------
extern "C" void kernel_launch(void* const* d_in, const int* in_sizes, int n_in,
                              void* d_out, int out_size)
{
    const int*   x    = (const int*)  d_in[0];
    const float* h0   = (const float*)d_in[1];
    const float* c0   = (const float*)d_in[2];
    const float* emb  = (const float*)d_in[3];
    const float* Wih0 = (const float*)d_in[4];
    const float* Whh0 = (const float*)d_in[5];
    const float* bih0 = (const float*)d_in[6];
    const float* bhh0 = (const float*)d_in[7];
    const float* Wih1 = (const float*)d_in[8];
    const float* Whh1 = (const float*)d_in[9];
    const float* bih1 = (const float*)d_in[10];
    const float* bhh1 = (const float*)d_in[11];
    const float* Wfc  = (const float*)d_in[12];
    const float* bfc  = (const float*)d_in[13];
    float* out = (float*)d_out;

    float *xg, *o0, *o1;
    cudaGetSymbolAddress((void**)&xg, g_xg);
    cudaGetSymbolAddress((void**)&o0, g_out0);
    cudaGetSymbolAddress((void**)&o1, g_out1);
    __nv_bfloat16 *a2, *b2;
    cudaGetSymbolAddress((void**)&a2, g_A2);
    cudaGetSymbolAddress((void**)&b2, g_B2);

    float* state_out = ((size_t)out_size >= LOGN + 4 * BB * HH) ? (out + LOGN) : nullptr;

    const int SMEM_SCAN = (HH * 32 + HH * 16 + 32 * 16 * 8) * 4;   // 212,992 B
    cudaFuncSetAttribute(lstm_scan, cudaFuncAttributeMaxDynamicSharedMemorySize, SMEM_SCAN);
    cudaFuncSetAttribute(fc_hmma, cudaFuncAttributeMaxDynamicSharedMemorySize, FC_SMEM);

    // weight split/expand (overlaps nothing critical; runs up front)
    split3<1><<<(VV * HH / 4 + 255) / 256, 256>>>(Wfc, b2, VV * HH / 4);

    // layer 0
    sgemm_tn<true, true><<<dim3(G4H / 128, M_ROWS / 128), 256>>>(
        emb, Wih0, bih0, bhh0, xg, M_ROWS, G4H, EE, x);
    fill_h0_kernel<<<(BB * HH + 255) / 256, 256>>>(h0);
    lstm_scan<<<128, 256, SMEM_SCAN>>>(xg, Whh0, c0, o0, state_out, 0);

    // layer 1
    sgemm_tn<false, true><<<dim3(G4H / 128, M_ROWS / 128), 256>>>(
        o0, Wih1, bih1, bhh1, xg, M_ROWS, G4H, HH, nullptr);
    fill_h0_kernel<<<(BB * HH + 255) / 256, 256>>>(h0 + BB * HH);
    lstm_scan<<<128, 256, SMEM_SCAN>>>(xg, Whh1, c0 + BB * HH, o1, state_out, 1);

    // activation split/expand, then tensor-core FC
    split3<0><<<(M_ROWS * HH / 4 + 255) / 256, 256>>>(o1, a2, M_ROWS * HH / 4);
    fc_hmma<<<dim3(M_ROWS / 128, VV / 128), 256, FC_SMEM>>>(a2, b2, bfc, out);
}

// round 5
// speedup vs baseline: 1.4292x; 1.0663x over previous
#include <cuda_runtime.h>
#include <cuda_bf16.h>
#include <cstdint>

// ---------------- problem constants ----------------
#define T_SEQ 512
#define BB    16
#define HH    1024
#define EE    512
#define VV    32000
#define G4H   4096
#define M_ROWS (BB * T_SEQ)                     // 8192
#define LOGN  ((size_t)M_ROWS * (size_t)VV)     // 262,144,000

// ---------------- device scratch (static globals: allowed) ----------------
__device__ float g_xg[(size_t)T_SEQ * BB * G4H];      // 134 MB, reused per layer
__device__ float g_out0[(size_t)M_ROWS * HH];         // layer-0 h sequence
__device__ float g_out1[(size_t)M_ROWS * HH];         // layer-1 h sequence
__device__ float g_hbuf[2 * HH * BB];                 // double buffer, [j][b] layout
__device__ unsigned g_bar;                            // zero-init
__device__ volatile unsigned g_epoch;                 // zero-init
__device__ __nv_bfloat16 g_A2[(size_t)M_ROWS * 3072]; // 50 MB  activations (hi|hi|lo)
__device__ __nv_bfloat16 g_B2[(size_t)VV * 3072];     // 197 MB Wfc (hi|lo|hi)
__device__ __nv_bfloat16 g_W2[(size_t)G4H * 3072];    // 25 MB  Wih (hi|lo|hi)

// ---------------- f32x2 packed-FMA helpers ----------------
typedef unsigned long long u64;
__device__ __forceinline__ u64 pack2(float v) {
    u64 r; asm("mov.b64 %0, {%1, %1};" : "=l"(r) : "f"(v)); return r;
}
__device__ __forceinline__ void ffma2(u64& c, u64 a, u64 b) {
    asm("fma.rn.f32x2 %0, %1, %2, %0;" : "+l"(c) : "l"(a), "l"(b));
}
__device__ __forceinline__ float2 unpack2(u64 v) {
    float lo, hi; asm("mov.b64 {%0, %1}, %2;" : "=f"(lo), "=f"(hi) : "l"(v));
    float2 f; f.x = lo; f.y = hi; return f;
}

// ---------------- base-ISA async-copy / ldmatrix / mma helpers ----------------
__device__ __forceinline__ uint32_t smem_u32(const void* p) {
    uint32_t a;
    asm("{ .reg .u64 t; cvta.to.shared.u64 t, %1; cvt.u32.u64 %0, t; }" : "=r"(a) : "l"(p));
    return a;
}
__device__ __forceinline__ void cpa16(uint32_t dst, const void* src) {
    asm volatile("cp.async.cg.shared.global [%0], [%1], 16;" :: "r"(dst), "l"(src));
}
__device__ __forceinline__ void cpa_commit() { asm volatile("cp.async.commit_group;" ::: "memory"); }
template<int N> __device__ __forceinline__ void cpa_wait() {
    asm volatile("cp.async.wait_group %0;" :: "n"(N) : "memory");
}
__device__ __forceinline__ void ldsm4(uint32_t& r0, uint32_t& r1, uint32_t& r2, uint32_t& r3,
                                      uint32_t a) {
    asm volatile("ldmatrix.sync.aligned.m8n8.x4.shared.b16 {%0,%1,%2,%3}, [%4];"
                 : "=r"(r0), "=r"(r1), "=r"(r2), "=r"(r3) : "r"(a));
}
__device__ __forceinline__ void mma_bf16(float* c, const uint32_t* a, const uint32_t* b) {
    asm volatile(
        "mma.sync.aligned.m16n8k16.row.col.f32.bf16.bf16.f32 "
        "{%0,%1,%2,%3}, {%4,%5,%6,%7}, {%8,%9}, {%0,%1,%2,%3};"
        : "+f"(c[0]), "+f"(c[1]), "+f"(c[2]), "+f"(c[3])
        : "r"(a[0]), "r"(a[1]), "r"(a[2]), "r"(a[3]), "r"(b[0]), "r"(b[1]));
}

// ---------------- split-expand: fp32 [rows][K] -> bf16 [rows][3K] ---------------
// MODE 0 (activations): segs (hi, hi, lo).  MODE 1 (weights): segs (hi, lo, hi).
// Optional row gather (gidx) for the embedding lookup fused into the split.
template<int MODE>
__global__ __launch_bounds__(256)
void split3(const float* __restrict__ src, const int* __restrict__ gidx,
            __nv_bfloat16* __restrict__ dst, int n4, int Kdiv4)
{
    int i = blockIdx.x * 256 + threadIdx.x;
    if (i >= n4) return;
    int row = i / Kdiv4;
    int c4  = i - row * Kdiv4;
    int K   = Kdiv4 * 4;
    const float* sp = gidx ? (src + (size_t)gidx[row] * K) : (src + (size_t)row * K);
    float4 v = *(const float4*)(sp + c4 * 4);
    __nv_bfloat16 h0 = __float2bfloat16(v.x), h1 = __float2bfloat16(v.y);
    __nv_bfloat16 h2 = __float2bfloat16(v.z), h3 = __float2bfloat16(v.w);
    __nv_bfloat16 l0 = __float2bfloat16(v.x - __bfloat162float(h0));
    __nv_bfloat16 l1 = __float2bfloat16(v.y - __bfloat162float(h1));
    __nv_bfloat16 l2 = __float2bfloat16(v.z - __bfloat162float(h2));
    __nv_bfloat16 l3 = __float2bfloat16(v.w - __bfloat162float(h3));
    __nv_bfloat162 hA(h0, h1), hB(h2, h3), lA(l0, l1), lB(l2, l3);
    size_t base = (size_t)row * (3 * K) + c4 * 4;
    __nv_bfloat162* d0 = (__nv_bfloat162*)(dst + base);
    __nv_bfloat162* d1 = (__nv_bfloat162*)(dst + base + K);
    __nv_bfloat162* d2 = (__nv_bfloat162*)(dst + base + 2 * K);
    d0[0] = hA; d0[1] = hB;
    if (MODE == 0) { d1[0] = hA; d1[1] = hB; d2[0] = lA; d2[1] = lB; }
    else           { d1[0] = lA; d1[1] = lB; d2[0] = hA; d2[1] = hB; }
}

// ---------------- generic HMMA GEMM (mma.sync bf16) ----------------------------
// C[M, N] = A2[M, Kexp] @ B2[N, Kexp]^T + bias1 (+ bias2)
// CTA tile 128x128, 8 warps of 64x32, BK=32, 3-stage cp.async pipeline,
// XOR-swizzled smem for conflict-free ldmatrix.
// REMAP: output row gm -> (gm % T_SEQ) * BB + (gm / T_SEQ)   (xg layout)
#define HM_BK      32
#define HM_STAGE_B 16384
#define HM_SMEM    (3 * HM_STAGE_B)     // 49152

__device__ __forceinline__ void hm_fill(uint32_t st, const __nv_bfloat16* a,
                                        const __nv_bfloat16* b, int tid, int Kexp)
{
#pragma unroll
    for (int i = tid; i < 512; i += 256) {
        int r = i >> 2, c = i & 3;
        uint32_t dst = st + r * 64 + ((c ^ ((r >> 1) & 3)) << 4);
        cpa16(dst, a + (size_t)r * Kexp + c * 8);
    }
#pragma unroll
    for (int i = tid; i < 512; i += 256) {
        int r = i >> 2, c = i & 3;
        uint32_t dst = st + 8192 + r * 64 + ((c ^ ((r >> 1) & 3)) << 4);
        cpa16(dst, b + (size_t)r * Kexp + c * 8);
    }
    cpa_commit();
}

template<bool REMAP, bool BIAS2>
__global__ __launch_bounds__(256, 2)
void hmma_tn(const __nv_bfloat16* __restrict__ A2, const __nv_bfloat16* __restrict__ B2,
             const float* __restrict__ bias1, const float* __restrict__ bias2,
             float* __restrict__ C, int Kexp, int N)
{
    extern __shared__ char smem[];
    const uint32_t sbase = smem_u32(smem);
    const int tid = threadIdx.x, wid = tid >> 5, lane = tid & 31;
    const int warp_m = wid & 1, warp_n = wid >> 1;          // 2 x 4 warp grid
    const int m0 = blockIdx.x * 128;                         // M fast => B L2 reuse
    const int n0 = blockIdx.y * 128;

    const __nv_bfloat16* aG = A2 + (size_t)m0 * Kexp;
    const __nv_bfloat16* bG = B2 + (size_t)n0 * Kexp;

    uint32_t aoff[4][2], boff[2][2];
#pragma unroll
    for (int mi = 0; mi < 4; ++mi)
#pragma unroll
        for (int ks = 0; ks < 2; ++ks) {
            int row = warp_m * 64 + mi * 16 + (lane & 15);
            int ch  = ks * 2 + (lane >> 4);
            aoff[mi][ks] = row * 64 + ((ch ^ ((row >> 1) & 3)) << 4);
        }
#pragma unroll
    for (int bi = 0; bi < 2; ++bi)
#pragma unroll
        for (int ks = 0; ks < 2; ++ks) {
            int row = warp_n * 32 + bi * 16 + (lane & 7) + ((lane >> 4) << 3);
            int ch  = ks * 2 + ((lane >> 3) & 1);
            boff[bi][ks] = 8192 + row * 64 + ((ch ^ ((row >> 1) & 3)) << 4);
        }

    float acc[4][4][4];
#pragma unroll
    for (int i = 0; i < 4; i++)
#pragma unroll
        for (int j = 0; j < 4; j++)
#pragma unroll
            for (int e = 0; e < 4; e++) acc[i][j][e] = 0.f;

    const int NKB = Kexp / HM_BK;
    hm_fill(sbase,              aG,         bG,         tid, Kexp);
    hm_fill(sbase + HM_STAGE_B, aG + HM_BK, bG + HM_BK, tid, Kexp);

    for (int kb = 0; kb < NKB; ++kb) {
        const int s = kb % 3;
        cpa_wait<1>();
        __syncthreads();
        if (kb + 2 < NKB)
            hm_fill(sbase + ((kb + 2) % 3) * HM_STAGE_B,
                    aG + (size_t)(kb + 2) * HM_BK, bG + (size_t)(kb + 2) * HM_BK, tid, Kexp);

        const uint32_t sb = sbase + s * HM_STAGE_B;
#pragma unroll
        for (int ks = 0; ks < 2; ++ks) {
            uint32_t a[4][4], b[2][4];
#pragma unroll
            for (int mi = 0; mi < 4; ++mi)
                ldsm4(a[mi][0], a[mi][1], a[mi][2], a[mi][3], sb + aoff[mi][ks]);
#pragma unroll
            for (int bi = 0; bi < 2; ++bi)
                ldsm4(b[bi][0], b[bi][1], b[bi][2], b[bi][3], sb + boff[bi][ks]);
#pragma unroll
            for (int mi = 0; mi < 4; ++mi)
#pragma unroll
                for (int ni = 0; ni < 4; ++ni)
                    mma_bf16(acc[mi][ni], a[mi], &b[ni >> 1][(ni & 1) * 2]);
        }
        __syncthreads();
    }

    // epilogue: direct f32 stores with bias (rows remapped for xg layout)
#pragma unroll
    for (int mi = 0; mi < 4; ++mi) {
        int gm = m0 + warp_m * 64 + mi * 16 + (lane >> 2);
        size_t r0 = REMAP ? (size_t)((gm & (T_SEQ - 1)) * BB + (gm >> 9)) : (size_t)gm;
        int gm8 = gm + 8;
        size_t r1 = REMAP ? (size_t)((gm8 & (T_SEQ - 1)) * BB + (gm8 >> 9)) : (size_t)gm8;
#pragma unroll
        for (int ni = 0; ni < 4; ++ni) {
            int col = n0 + warp_n * 32 + ni * 8 + (lane & 3) * 2;
            float2 bv = *(const float2*)(bias1 + col);
            if (BIAS2) {
                float2 b2v = *(const float2*)(bias2 + col);
                bv.x += b2v.x; bv.y += b2v.y;
            }
            float2 v0; v0.x = acc[mi][ni][0] + bv.x; v0.y = acc[mi][ni][1] + bv.y;
            float2 v1; v1.x = acc[mi][ni][2] + bv.x; v1.y = acc[mi][ni][3] + bv.y;
            *(float2*)(C + r0 * (size_t)N + col) = v0;
            *(float2*)(C + r1 * (size_t)N + col) = v1;
        }
    }
}

// ---------------- h0 transpose fill: g_hbuf[0][j*16+b] = h0[b][j] --------------
__global__ void fill_h0_kernel(const float* __restrict__ h0)
{
    int i = blockIdx.x * 256 + threadIdx.x;
    if (i < BB * HH) {
        int b = i >> 10, j = i & (HH - 1);
        g_hbuf[j * BB + b] = h0[i];
    }
}

// ---------------- persistent LSTM scan (FFMA2 inner loop) ----------------------
__device__ __forceinline__ float sigm(float x) { return 1.f / (1.f + expf(-x)); }

__global__ __launch_bounds__(256)
void lstm_scan(const float* __restrict__ xg, const float* __restrict__ Whh,
               const float* __restrict__ c0, float* __restrict__ outSeq,
               float* __restrict__ state_out, int layer)
{
    extern __shared__ float sm[];
    float* ws  = sm;                          // [1024][32]  128 KB
    float* hs  = sm + HH * 32;                // [1024][16]   64 KB
    float* red = sm + HH * 32 + HH * 16;      // [32][16][8]  16 KB
    const int tid = threadIdx.x, cta = blockIdx.x;
    const int warp = tid >> 5, lane = tid & 31;
    const int rg = lane & 7, bg = lane >> 3;

    for (int idx = tid; idx < 32 * 256; idx += 256) {
        int r  = idx >> 8;
        int k4 = (idx & 255) * 4;
        int grow = (r >> 3) * HH + cta * 8 + (r & 7);
        float4 w = *(const float4*)(Whh + (size_t)grow * HH + k4);
        ws[(k4 + 0) * 32 + r] = w.x; ws[(k4 + 1) * 32 + r] = w.y;
        ws[(k4 + 2) * 32 + r] = w.z; ws[(k4 + 3) * 32 + r] = w.w;
    }

    const int fb = tid >> 3, fj = tid & 7;
    float c_reg = 0.f;
    if (tid < 128) c_reg = c0[fb * HH + cta * 8 + fj];

    int cur = 0;
    const int k0 = warp * 128;
    for (int t = 0; t < T_SEQ; ++t) {
        const float4* hb = (const float4*)(g_hbuf + cur * (HH * BB));
        float4* hs4 = (float4*)hs;
#pragma unroll
        for (int i = 0; i < 16; ++i) hs4[tid + i * 256] = __ldcg(hb + tid + i * 256);
        __syncthreads();

        u64 acc2[4][2];
#pragma unroll
        for (int i = 0; i < 4; i++) { acc2[i][0] = 0ULL; acc2[i][1] = 0ULL; }

#pragma unroll 4
        for (int k = k0; k < k0 + 128; ++k) {
            ulonglong2 hv = *(const ulonglong2*)&hs[k * 16 + bg * 4];
            float4 wv = *(const float4*)&ws[k * 32 + rg * 4];
            u64 w0 = pack2(wv.x), w1 = pack2(wv.y), w2 = pack2(wv.z), w3 = pack2(wv.w);
            ffma2(acc2[0][0], w0, hv.x); ffma2(acc2[0][1], w0, hv.y);
            ffma2(acc2[1][0], w1, hv.x); ffma2(acc2[1][1], w1, hv.y);
            ffma2(acc2[2][0], w2, hv.x); ffma2(acc2[2][1], w2, hv.y);
            ffma2(acc2[3][0], w3, hv.x); ffma2(acc2[3][1], w3, hv.y);
        }
#pragma unroll
        for (int i = 0; i < 4; i++) {
            float2 p0 = unpack2(acc2[i][0]);
            float2 p1 = unpack2(acc2[i][1]);
            float* rp = &red[(((rg * 4 + i) << 4) + bg * 4) * 8 + warp];
            rp[0 * 8] = p0.x; rp[1 * 8] = p0.y; rp[2 * 8] = p1.x; rp[3 * 8] = p1.y;
        }
        __syncthreads();

        if (tid < 128) {
            int jg = cta * 8 + fj;
            float s[4];
#pragma unroll
            for (int g = 0; g < 4; ++g) {
                const float* rp = &red[(((g * 8 + fj) << 4) + fb) * 8];
                float sum = rp[0] + rp[1] + rp[2] + rp[3] + rp[4] + rp[5] + rp[6] + rp[7];
                s[g] = sum + xg[((size_t)(t * BB + fb)) * G4H + g * HH + jg];
            }
            float ci = sigm(s[0]), cf = sigm(s[1]);
            float cg = tanhf(s[2]), co = sigm(s[3]);
            c_reg = cf * c_reg + ci * cg;
            float hnew = co * tanhf(c_reg);
            outSeq[((size_t)fb * T_SEQ + t) * HH + jg] = hnew;
            g_hbuf[(cur ^ 1) * (HH * BB) + jg * BB + fb] = hnew;
            if (t == T_SEQ - 1 && state_out) {
                state_out[(size_t)layer * BB * HH + fb * HH + jg] = hnew;
                state_out[2 * (size_t)BB * HH + (size_t)layer * BB * HH + fb * HH + jg] = c_reg;
            }
        }

        __syncthreads();
        if (tid == 0) {
            unsigned e = g_epoch;
            __threadfence();
            if (atomicAdd(&g_bar, 1u) == (unsigned)gridDim.x - 1u) {
                g_bar = 0;
                __threadfence();
                g_epoch = e + 1;
            } else {
                while (g_epoch == e) { }
            }
        }
        __syncthreads();
        cur ^= 1;
    }
}

// ---------------- launch -------------------------------------------------------
extern "C" void kernel_launch(void* const* d_in, const int* in_sizes, int n_in,
                              void* d_out, int out_size)
{
    const int*   x    = (const int*)  d_in[0];
    const float* h0   = (const float*)d_in[1];
    const float* c0   = (const float*)d_in[2];
    const float* emb  = (const float*)d_in[3];
    const float* Wih0 = (const float*)d_in[4];
    const float* Whh0 = (const float*)d_in[5];
    const float* bih0 = (const float*)d_in[6];
    const float* bhh0 = (const float*)d_in[7];
    const float* Wih1 = (const float*)d_in[8];
    const float* Whh1 = (const float*)d_in[9];
    const float* bih1 = (const float*)d_in[10];
    const float* bhh1 = (const float*)d_in[11];
    const float* Wfc  = (const float*)d_in[12];
    const float* bfc  = (const float*)d_in[13];
    float* out = (float*)d_out;

    float *xg, *o0, *o1;
    cudaGetSymbolAddress((void**)&xg, g_xg);
    cudaGetSymbolAddress((void**)&o0, g_out0);
    cudaGetSymbolAddress((void**)&o1, g_out1);
    __nv_bfloat16 *a2, *b2, *w2;
    cudaGetSymbolAddress((void**)&a2, g_A2);
    cudaGetSymbolAddress((void**)&b2, g_B2);
    cudaGetSymbolAddress((void**)&w2, g_W2);

    float* state_out = ((size_t)out_size >= LOGN + 4 * BB * HH) ? (out + LOGN) : nullptr;

    const int SMEM_SCAN = (HH * 32 + HH * 16 + 32 * 16 * 8) * 4;   // 212,992 B
    cudaFuncSetAttribute(lstm_scan, cudaFuncAttributeMaxDynamicSharedMemorySize, SMEM_SCAN);
    cudaFuncSetAttribute(hmma_tn<true, true>,   cudaFuncAttributeMaxDynamicSharedMemorySize, HM_SMEM);
    cudaFuncSetAttribute(hmma_tn<false, false>, cudaFuncAttributeMaxDynamicSharedMemorySize, HM_SMEM);

    // Wfc split (hi|lo|hi) — biggest split, up front
    split3<1><<<(VV * HH / 4 + 255) / 256, 256>>>(Wfc, nullptr, b2, VV * HH / 4, HH / 4);

    // ---- layer 0: xg0 = gather(emb,x) @ Wih0^T + bih0 + bhh0 (HMMA, Kexp=1536)
    split3<0><<<(M_ROWS * EE / 4 + 255) / 256, 256>>>(emb, x, a2, M_ROWS * EE / 4, EE / 4);
    split3<1><<<(G4H * EE / 4 + 255) / 256, 256>>>(Wih0, nullptr, w2, G4H * EE / 4, EE / 4);
    hmma_tn<true, true><<<dim3(M_ROWS / 128, G4H / 128), 256, HM_SMEM>>>(
        a2, w2, bih0, bhh0, xg, 3 * EE, G4H);
    fill_h0_kernel<<<(BB * HH + 255) / 256, 256>>>(h0);
    lstm_scan<<<128, 256, SMEM_SCAN>>>(xg, Whh0, c0, o0, state_out, 0);

    // ---- layer 1: xg1 = out0 @ Wih1^T + bih1 + bhh1 (HMMA, Kexp=3072)
    split3<0><<<(M_ROWS * HH / 4 + 255) / 256, 256>>>(o0, nullptr, a2, M_ROWS * HH / 4, HH / 4);
    split3<1><<<(G4H * HH / 4 + 255) / 256, 256>>>(Wih1, nullptr, w2, G4H * HH / 4, HH / 4);
    hmma_tn<true, true><<<dim3(M_ROWS / 128, G4H / 128), 256, HM_SMEM>>>(
        a2, w2, bih1, bhh1, xg, 3 * HH, G4H);
    fill_h0_kernel<<<(BB * HH + 255) / 256, 256>>>(h0 + BB * HH);
    lstm_scan<<<128, 256, SMEM_SCAN>>>(xg, Whh1, c0 + BB * HH, o1, state_out, 1);

    // ---- FC: logits = out1 @ Wfc^T + bfc (HMMA, Kexp=3072)
    split3<0><<<(M_ROWS * HH / 4 + 255) / 256, 256>>>(o1, nullptr, a2, M_ROWS * HH / 4, HH / 4);
    hmma_tn<false, false><<<dim3(M_ROWS / 128, VV / 128), 256, HM_SMEM>>>(
        a2, b2, bfc, nullptr, out, 3 * HH, VV);
}